// round 7
// baseline (speedup 1.0000x reference)
#include <cuda_runtime.h>

#define NB      512
#define NL      512
#define NC      8
#define NCHK    16        // chunks per batch
#define STEPS   32        // increments per chunk (last: 31 real + 1 zero)
#define CSTRIDE 264       // floats per chunk in staging (32*8 + 8 pad)
#define SIGSZ   584       // 8 + 64 + 512
#define S2OFF   8
#define S3OFF   72

typedef unsigned long long ull;

__device__ __forceinline__ void ffma2(ull& d, ull a, ull b) {
    asm("fma.rn.f32x2 %0, %1, %2, %0;" : "+l"(d) : "l"(a), "l"(b));
}
__device__ __forceinline__ ull fma2n(ull a, ull b, ull c) {
    ull r; asm("fma.rn.f32x2 %0, %1, %2, %3;" : "=l"(r) : "l"(a), "l"(b), "l"(c)); return r;
}
__device__ __forceinline__ ull dup2(float x) {
    ull r; asm("mov.b64 %0, {%1, %1};" : "=l"(r) : "f"(x)); return r;
}
__device__ __forceinline__ void unpk2(ull v, float& lo, float& hi) {
    asm("mov.b64 {%0, %1}, %2;" : "=f"(lo), "=f"(hi) : "l"(v));
}

// ---------------------------------------------------------------------------
// One block = one batch. 256 threads = 16 chunks x 16 threads.
// Thread (g, h): i = h&7, chalf = h>>3, c0 = 4*chalf. Owns:
//   S1[i] (redundant across chalf), S2[i, c0..c0+3] (2 x f32x2 over c-pairs),
//   S3[i, c0+cl, :] for cl=0..3 (4 x 4 f32x2 packed over d-pairs).
// Per step (OLD state on RHS):
//   coef[i,c] = S2[i,c] + dx[c]*(S1[i]/2 + dxi/6)
//   S3[i,c,d] += coef * dx[d]
//   S2[i,c]   += dx[c]*(S1[i] + dxi/2)
//   S1[i]     += dxi
// Then a 4-level Chen tree combine in shared folds 16 segment sigs into one.
// ---------------------------------------------------------------------------
__global__ __launch_bounds__(256) void sig_fused_kernel(
    const float* __restrict__ path, float* __restrict__ out)
{
    const int b     = blockIdx.x;
    const int t     = threadIdx.x;     // 0..255
    const int g     = t >> 4;          // chunk 0..15
    const int h     = t & 15;
    const int i     = h & 7;           // level-1 row
    const int chalf = h >> 3;
    const int c0    = chalf * 4;       // owned c-range start

    // Union: staging (16*264 = 4224 fl) reused as segment sigs (16*584 fl).
    __shared__ __align__(16) float smem_u[NCHK * SIGSZ];   // 37376 B
    float* sinc = smem_u;
    float* sseg = smem_u;

    const float* prow = path + (size_t)b * NL * NC;

    // ---- Stage increments (chunk-padded layout; zero row for the tail) ----
    for (int r = t; r < NCHK * STEPS; r += 256) {
        float* w = sinc + (r >> 5) * CSTRIDE + (r & 31) * NC;
        if (r < NL - 1) {
            const float4* p = (const float4*)(prow + r * NC);
            float4 a0 = p[0], a1 = p[1], b0 = p[2], b1 = p[3];
            ((float4*)w)[0] = make_float4(b0.x - a0.x, b0.y - a0.y, b0.z - a0.z, b0.w - a0.w);
            ((float4*)w)[1] = make_float4(b1.x - a1.x, b1.y - a1.y, b1.z - a1.z, b1.w - a1.w);
        } else {
            ((float4*)w)[0] = make_float4(0.f, 0.f, 0.f, 0.f);
            ((float4*)w)[1] = make_float4(0.f, 0.f, 0.f, 0.f);
        }
    }
    __syncthreads();

    float s1 = 0.f;
    ull s2p[2] = {0ull, 0ull};            // {S2[i,c0..c0+1]}, {S2[i,c0+2..c0+3]}
    ull s3[4][4];                         // s3[cl][dp] = {S3[i,c0+cl,2dp], ...2dp+1}
    #pragma unroll
    for (int cl = 0; cl < 4; cl++)
        #pragma unroll
        for (int dp = 0; dp < 4; dp++) s3[cl][dp] = 0ull;

    const float* myc = sinc + g * CSTRIDE;

    #pragma unroll 4
    for (int s = 0; s < STEPS; s++) {
        const float* row = myc + s * NC;
        ulonglong2 lo  = *(const ulonglong2*)row;         // {dx0,dx1},{dx2,dx3}
        ulonglong2 hi  = *(const ulonglong2*)(row + 4);   // {dx4,dx5},{dx6,dx7}
        ulonglong2 dcv = *(const ulonglong2*)(row + c0);  // owned c-slice (2 pairs)
        float dxi = row[i];                               // broadcast LDS

        ull dx2[4] = {lo.x, lo.y, hi.x, hi.y};

        float hs = fmaf(dxi, 1.f / 6.f, 0.5f * s1);   // S1/2 + dxi/6
        float gs = fmaf(dxi, 0.5f, s1);               // S1 + dxi/2
        ull h2 = dup2(hs), g2 = dup2(gs);

        ull coef0 = fma2n(h2, dcv.x, s2p[0]);
        ull coef1 = fma2n(h2, dcv.y, s2p[1]);
        s2p[0]    = fma2n(g2, dcv.x, s2p[0]);
        s2p[1]    = fma2n(g2, dcv.y, s2p[1]);

        float cf0, cf1, cf2, cf3;
        unpk2(coef0, cf0, cf1);
        unpk2(coef1, cf2, cf3);
        ull cd0 = dup2(cf0), cd1 = dup2(cf1), cd2 = dup2(cf2), cd3 = dup2(cf3);

        #pragma unroll
        for (int dp = 0; dp < 4; dp++) {
            ffma2(s3[0][dp], cd0, dx2[dp]);
            ffma2(s3[1][dp], cd1, dx2[dp]);
            ffma2(s3[2][dp], cd2, dx2[dp]);
            ffma2(s3[3][dp], cd3, dx2[dp]);
        }
        s1 += dxi;
    }
    __syncthreads();   // all staging reads done before sseg overwrites

    // ---- Write segment signature ----
    {
        float* S = sseg + g * SIGSZ;
        if (h < 8) S[h] = s1;                       // chalf==0 writes S1
        *(ull*)(S + S2OFF + i * 8 + c0)     = s2p[0];
        *(ull*)(S + S2OFF + i * 8 + c0 + 2) = s2p[1];
        #pragma unroll
        for (int cl = 0; cl < 4; cl++)
            #pragma unroll
            for (int dp = 0; dp < 4; dp++)
                *(ull*)(S + S3OFF + i * 64 + (c0 + cl) * 8 + 2 * dp) = s3[cl][dp];
    }
    __syncthreads();

    // ---- Chen tree combine: 16 -> 8 -> 4 -> 2 -> 1 (result in sseg[0]) ----
    //   C1 = A1 + B1
    //   C2[i,c]   = A2 + B2 + A1[i]*B1[c]
    //   C3[i,c,d] = A3 + B3 + A1[i]*B2[c,d] + A2[i,c]*B1[d]
    #pragma unroll
    for (int st = 1; st < NCHK; st <<= 1) {
        const int work = (NCHK / (2 * st)) * 64;
        for (int base = 0; base < work; base += 256) {
            const int w   = base + t;
            const bool act = w < work;
            const int m   = w >> 6;
            const int lt  = w & 63;
            const int i2  = lt >> 3;
            const int c2  = lt & 7;
            float* A = sseg + (size_t)(2 * st * m) * SIGSZ;
            const float* B = sseg + (size_t)(2 * st * m + st) * SIGSZ;

            float na1 = 0.f, na2 = 0.f, na3[8];
            #pragma unroll
            for (int d = 0; d < 8; d++) na3[d] = 0.f;

            if (act) {
                float a1i = A[i2];
                float a2  = A[S2OFF + lt];
                const float4* a3p = (const float4*)(A + S3OFF + lt * 8);
                float4 av0 = a3p[0], av1 = a3p[1];
                float a3l[8] = {av0.x, av0.y, av0.z, av0.w, av1.x, av1.y, av1.z, av1.w};

                const float4* b1p = (const float4*)B;
                float4 bv0 = b1p[0], bv1 = b1p[1];
                float b1l[8] = {bv0.x, bv0.y, bv0.z, bv0.w, bv1.x, bv1.y, bv1.z, bv1.w};

                float b2t = B[S2OFF + lt];
                const float4* b2p = (const float4*)(B + S2OFF + c2 * 8);
                float4 cv0 = b2p[0], cv1 = b2p[1];
                float b2r[8] = {cv0.x, cv0.y, cv0.z, cv0.w, cv1.x, cv1.y, cv1.z, cv1.w};

                const float4* b3p = (const float4*)(B + S3OFF + lt * 8);
                float4 dv0 = b3p[0], dv1 = b3p[1];
                float b3l[8] = {dv0.x, dv0.y, dv0.z, dv0.w, dv1.x, dv1.y, dv1.z, dv1.w};

                #pragma unroll
                for (int d = 0; d < 8; d++)
                    na3[d] = fmaf(a2, b1l[d], fmaf(a1i, b2r[d], a3l[d] + b3l[d]));

                na2 = fmaf(a1i, b1l[c2], a2 + b2t);
                if (lt < 8) na1 = A[lt] + B[lt];
            }
            __syncthreads();   // reads complete before writes
            if (act) {
                if (lt < 8) A[lt] = na1;
                A[S2OFF + lt] = na2;
                float4* o = (float4*)(A + S3OFF + lt * 8);
                o[0] = make_float4(na3[0], na3[1], na3[2], na3[3]);
                o[1] = make_float4(na3[4], na3[5], na3[6], na3[7]);
            }
            __syncthreads();
        }
    }

    // ---- Store final signature (coalesced) ----
    float* o = out + (size_t)b * SIGSZ;
    for (int k = t; k < SIGSZ; k += 256)
        o[k] = sseg[k];
}

extern "C" void kernel_launch(void* const* d_in, const int* in_sizes, int n_in,
                              void* d_out, int out_size) {
    const float* path = (const float*)d_in[0];
    float* out = (float*)d_out;
    sig_fused_kernel<<<NB, 256>>>(path, out);
}